// round 10
// baseline (speedup 1.0000x reference)
#include <cuda_runtime.h>
#include <cstdint>

#define BATCH 16
#define NANCH 25200
#define NCLS  80
#define TOPK  2048
#define CAND  4096
#define NBIN  16384
#define KBASE 0x3E800000u
#define FULLM 0xFFFFFFFFu

// ---------------- scratch (no allocations allowed) ----------------
__device__ float              g_scores[BATCH * NANCH];
__device__ int                g_labels[BATCH * NANCH];
__device__ unsigned           g_hist[BATCH * NBIN];              // 1MB score histogram
__device__ float              g_top_scores[BATCH * TOPK];
__device__ float4             g_top_boxes[BATCH * TOPK];
__device__ int                g_top_labels[BATCH * TOPK];
__device__ unsigned long long g_mask[(size_t)BATCH * TOPK * 32]; // successor masks (j>i), 8MB
__device__ unsigned long long g_rownz[BATCH * 32];               // per-row nonzero bitmap

// ---------------- Stage 0: zero histogram (graph-replay safe) ----------------
__global__ __launch_bounds__(1024) void k_zero()
{
    g_hist[blockIdx.x * 1024 + threadIdx.x] = 0u;
}

// ---------------- Stage 1: per-anchor max/argmax + fused score histogram ----------------
__global__ __launch_bounds__(256) void k_scores(const float* __restrict__ obj,
                                                const float* __restrict__ cls)
{
    int gwarp = (blockIdx.x * 256 + threadIdx.x) >> 5;
    int lane  = threadIdx.x & 31;
    if (gwarp >= BATCH * NANCH) return;
    const float* p = cls + (size_t)gwarp * NCLS;

    // probs are non-negative -> float bits are order-preserving as u32
    unsigned b0 = __float_as_uint(p[lane]);
    unsigned b1 = __float_as_uint(p[lane + 32]);
    unsigned b2 = (lane < 16) ? __float_as_uint(p[lane + 64]) : 0u;
    unsigned lm = max(b0, max(b1, b2));
    unsigned m  = __reduce_max_sync(FULLM, lm);

    unsigned idx;
    if (b0 == m)                    idx = (unsigned)lane;
    else if (b1 == m)               idx = (unsigned)(lane + 32);
    else if (lane < 16 && b2 == m)  idx = (unsigned)(lane + 64);
    else                            idx = 0x7FFFFFFFu;
    unsigned mi = __reduce_min_sync(FULLM, idx);

    if (lane == 0) {
        float s = obj[gwarp] * __uint_as_float(m);   // == max(obj*p) bitwise
        float sc = (s > 0.25f) ? s : 0.0f;           // conf filter
        g_scores[gwarp] = sc;
        g_labels[gwarp] = (int)mi;
        if (sc > 0.0f) {
            unsigned key = __float_as_uint(sc);      // key in (KBASE, KBASE+2^24]
            unsigned bin = (key - KBASE) >> 10;
            if (bin > NBIN - 1) bin = NBIN - 1;
            atomicAdd(&g_hist[(gwarp / NANCH) * NBIN + bin], 1u);
        }
    }
}

// ---------------- Stage 2: threshold from histogram + gather + exact top-k sort ----------------
__global__ __launch_bounds__(1024) void k_select(const float4* __restrict__ boxes)
{
    __shared__ unsigned long long s_arr[CAND];  // 32KB
    __shared__ int                s_wsum[32];
    __shared__ int                s_L;
    __shared__ int                s_cnt;

    const int b    = blockIdx.x;
    const int tid  = threadIdx.x;
    const int warp = tid >> 5;
    const int lane = tid & 31;
    const unsigned* hist = g_hist + b * NBIN;
    const float* sc = g_scores + b * NANCH;

    // chunk t covers bins [NBIN-16(t+1), NBIN-16t) -- ascending t == descending score
    int hi = NBIN - 16 * tid;
    int sum = 0;
    #pragma unroll
    for (int k = 1; k <= 16; ++k) sum += (int)hist[hi - k];

    // block inclusive scan over t (warp shfl scan + warp-total scan)
    int v = sum;
    #pragma unroll
    for (int off = 1; off < 32; off <<= 1) {
        int n = __shfl_up_sync(FULLM, v, off);
        if (lane >= off) v += n;
    }
    if (lane == 31) s_wsum[warp] = v;
    if (tid == 0) s_L = 0;
    __syncthreads();
    if (warp == 0) {
        int w = s_wsum[lane];
        #pragma unroll
        for (int off = 1; off < 32; off <<= 1) {
            int n = __shfl_up_sync(FULLM, w, off);
            if (lane >= off) w += n;
        }
        s_wsum[lane] = w;
    }
    __syncthreads();
    int cum = v + ((warp > 0) ? s_wsum[warp - 1] : 0);   // inclusive prefix
    int total = s_wsum[31];

    if (total >= TOPK) {
        int prev = cum - sum;                            // exclusive prefix
        if (cum >= TOPK && prev < TOPK) {                // exactly one thread
            int acc = prev, L = 0;
            for (int k = 1; k <= 16; ++k) {
                int bidx = hi - k;
                acc += (int)hist[bidx];
                if (acc >= TOPK) { L = bidx; break; }
            }
            s_L = L;
        }
    }
    if (tid == 0) s_cnt = 0;
    if (tid < 32) g_rownz[b * 32 + tid] = 0ull;          // zero nz bitmap for stage 3
    __syncthreads();
    const int L = s_L;

    // ballot-aggregated gather of all candidates with bin >= L (superset of exact top-K)
    const int iters = (NANCH + 1023) / 1024;             // uniform trip count
    for (int it = 0; it < iters; ++it) {
        int i = tid + it * 1024;
        bool take = false; unsigned k = 0;
        if (i < NANCH) {
            float s = sc[i];
            if (s > 0.0f) {
                k = __float_as_uint(s);
                unsigned bin = (k - KBASE) >> 10;
                if (bin > NBIN - 1) bin = NBIN - 1;
                take = ((int)bin >= L);
            }
        }
        unsigned bal = __ballot_sync(FULLM, take);
        if (bal) {
            int leader = __ffs(bal) - 1;
            int pos = 0;
            if (lane == leader) pos = atomicAdd(&s_cnt, __popc(bal));
            pos = __shfl_sync(FULLM, pos, leader);
            if (take) {
                int my = pos + __popc(bal & ((1u << lane) - 1u));
                if (my < CAND)
                    s_arr[my] = ((unsigned long long)k << 32) | (unsigned)(0xFFFFFFFFu - (unsigned)i);
            }
        }
    }
    __syncthreads();
    int cnt = s_cnt; if (cnt > CAND) cnt = CAND;
    for (int p = cnt + tid; p < CAND; p += 1024) s_arr[p] = 0ull;
    __syncthreads();

    // bitonic sort descending on (score desc, idx asc) -- matches lax.top_k exactly
    for (int kk = 2; kk <= CAND; kk <<= 1) {
        for (int j = kk >> 1; j > 0; j >>= 1) {
            for (int p = tid; p < CAND / 2; p += 1024) {
                int i = ((p & ~(j - 1)) << 1) | (p & (j - 1));
                int l = i | j;
                unsigned long long a = s_arr[i], c = s_arr[l];
                bool desc = ((i & kk) == 0);
                if (desc ? (a < c) : (a > c)) { s_arr[i] = c; s_arr[l] = a; }
            }
            __syncthreads();
        }
    }

    for (int j = tid; j < TOPK; j += 1024) {
        unsigned long long c = s_arr[j];
        unsigned key = (unsigned)(c >> 32);
        int o = b * TOPK + j;
        g_top_scores[o] = __uint_as_float(key);
        if (key) {
            unsigned idx = 0xFFFFFFFFu - (unsigned)(c & 0xFFFFFFFFull);
            g_top_boxes[o]  = boxes[(size_t)b * NANCH + idx];
            g_top_labels[o] = g_labels[b * NANCH + idx];
        } else {
            g_top_boxes[o]  = make_float4(0.f, 0.f, 0.f, 0.f);
            g_top_labels[o] = 0;
        }
    }
}

// ---------------- Stage 3a: successor IoU bitmask (j > i), 32 rows/block ----------------
__global__ __launch_bounds__(1024) void k_mask()
{
    __shared__ float4 sbox[TOPK];   // 32KB
    __shared__ float  sarea[TOPK];  // 8KB
    const int b   = blockIdx.y;
    const int tid = threadIdx.x;
    for (int j = tid; j < TOPK; j += 1024) {
        float4 v = g_top_boxes[b * TOPK + j];
        sbox[j]  = v;
        sarea[j] = (v.z - v.x) * (v.w - v.y);   // same op order as reference
    }
    __syncthreads();

    const int warp = tid >> 5, lane = tid & 31;
    const int i = blockIdx.x * 32 + warp;
    const float4 bi = sbox[i];
    const float  ai = sarea[i];

    unsigned long long word = 0ull;
    int j0 = lane * 64;
    int js = (j0 > i + 1) ? j0 : (i + 1);   // successors only
    int je = j0 + 64;
    for (int j = js; j < je; ++j) {
        float4 bj = sbox[j];
        float ltx = fmaxf(bi.x, bj.x), lty = fmaxf(bi.y, bj.y);
        float rbx = fminf(bi.z, bj.z), rby = fminf(bi.w, bj.w);
        float w = rbx - ltx, h = rby - lty;
        if (w > 0.0f && h > 0.0f) {
            float inter = w * h;
            float iou = __fdiv_rn(inter, (ai + sarea[j]) - inter); // IEEE div
            if (iou > 0.45f) word |= 1ull << (j & 63);
        }
    }
    g_mask[((size_t)(b * TOPK + i)) * 32 + lane] = word;
    unsigned nzb = __ballot_sync(FULLM, word != 0ull);
    if (lane == 0 && nzb)
        atomicOr(&g_rownz[b * 32 + (i >> 6)], 1ull << (i & 63));
}

// ---------------- Stage 3b: double-buffered shared-memory greedy resolve (128 thr) ----------------
__global__ __launch_bounds__(128) void k_resolve(float* __restrict__ out_boxes,
                                                 float* __restrict__ out_scores,
                                                 float* __restrict__ out_labels)
{
    __shared__ unsigned long long s_buf[2][64 * 32];   // 2 x 16KB double buffer
    __shared__ unsigned long long s_alive[32], s_keep[32];
    const int b = blockIdx.x, tid = threadIdx.x, warp = tid >> 5, lane = tid & 31;

    // alive bits: each of 4 warps covers 8 chunks of 64 rows
    #pragma unroll
    for (int k = 0; k < 8; ++k) {
        int chunk = warp * 8 + k;
        bool a0 = g_top_scores[b * TOPK + chunk * 64 + lane] > 0.0f;
        bool a1 = g_top_scores[b * TOPK + chunk * 64 + 32 + lane] > 0.0f;
        unsigned lo = __ballot_sync(FULLM, a0);
        unsigned hiv = __ballot_sync(FULLM, a1);
        if (lane == 0) s_alive[chunk] = ((unsigned long long)hiv << 32) | (unsigned long long)lo;
    }

    const unsigned long long* mbase = g_mask + (size_t)b * TOPK * 32;

    for (int i = tid; i < 2048; i += 128) s_buf[0][i] = mbase[i];   // prefetch block 0
    __syncthreads();

    unsigned long long rm = 0ull, alv = 0ull, nzw = 0ull;  // warp 0: lane w owns word w
    if (warp == 0) { nzw = g_rownz[b * 32 + lane]; alv = s_alive[lane]; }

    for (int g = 0; g < 32; ++g) {
        if (warp > 0) {
            if (g < 31) {                                   // producer: prefetch block g+1
                const unsigned long long* src = mbase + (size_t)(g + 1) * 2048;
                unsigned long long* dst = s_buf[(g + 1) & 1];
                for (int i = tid - 32; i < 2048; i += 96) dst[i] = src[i];
            }
        } else {
            const unsigned long long* buf = s_buf[g & 1];   // consumer: resolve block g
            unsigned long long rmB = __shfl_sync(FULLM, rm,  g);
            unsigned long long alB = __shfl_sync(FULLM, alv, g);
            unsigned long long nzB = __shfl_sync(FULLM, nzw, g);
            unsigned long long cand = alB & ~rmB & nzB;     // only rows that can suppress
            unsigned long long rem = 0ull, kept = 0ull;

            while (cand) {                                  // uniform across the warp
                int r = __ffsll((long long)cand) - 1;
                cand &= cand - 1ull;
                kept |= 1ull << r;
                rem  |= buf[r * 32 + g];                    // broadcast LDS (diagonal word)
                cand &= ~rem;
            }
            if (lane == g) rm |= rem;

            unsigned long long a0 = 0, a1 = 0, a2 = 0, a3 = 0;  // rotate 4 accumulators
            unsigned long long kz = kept;
            while (kz) {
                int r0 = __ffsll((long long)kz) - 1; kz &= kz - 1ull;
                a0 |= buf[r0 * 32 + lane];
                if (kz) { int r1 = __ffsll((long long)kz) - 1; kz &= kz - 1ull; a1 |= buf[r1 * 32 + lane]; }
                if (kz) { int r2 = __ffsll((long long)kz) - 1; kz &= kz - 1ull; a2 |= buf[r2 * 32 + lane]; }
                if (kz) { int r3 = __ffsll((long long)kz) - 1; kz &= kz - 1ull; a3 |= buf[r3 * 32 + lane]; }
            }
            rm |= (a0 | a1) | (a2 | a3);
        }
        __syncthreads();
    }

    if (warp == 0) s_keep[lane] = alv & ~rm;
    __syncthreads();

    float4* ob = (float4*)out_boxes;
    for (int j = tid; j < TOPK; j += 128) {
        int o = b * TOPK + j;
        bool kp = ((s_keep[j >> 6] >> (j & 63)) & 1ull) != 0ull;
        float f = kp ? 1.0f : 0.0f;
        float4 bx = g_top_boxes[o];
        ob[o] = make_float4(bx.x * f, bx.y * f, bx.z * f, bx.w * f);
        out_scores[o] = kp ? g_top_scores[o] : 0.0f;
        out_labels[o] = kp ? (float)g_top_labels[o] : 0.0f;
    }
}

// ---------------- launch ----------------
extern "C" void kernel_launch(void* const* d_in, const int* in_sizes, int n_in,
                              void* d_out, int out_size)
{
    const float* boxes = (const float*)d_in[0];   // [16,25200,4]
    const float* obj   = (const float*)d_in[1];   // [16,25200]
    const float* cls   = (const float*)d_in[2];   // [16,25200,80]
    float* out = (float*)d_out;

    (void)in_sizes; (void)n_in; (void)out_size;

    k_zero<<<BATCH * NBIN / 1024, 1024>>>();

    int rows = BATCH * NANCH;
    int blocks1 = (rows * 32 + 255) / 256;         // warp per row
    k_scores<<<blocks1, 256>>>(obj, cls);

    k_select<<<BATCH, 1024>>>((const float4*)boxes);

    dim3 gm(TOPK / 32, BATCH);
    k_mask<<<gm, 1024>>>();

    float* out_boxes  = out;
    float* out_scores = out + (size_t)BATCH * TOPK * 4;
    float* out_labels = out + (size_t)BATCH * TOPK * 5;
    k_resolve<<<BATCH, 128>>>(out_boxes, out_scores, out_labels);
}

// round 15
// speedup vs baseline: 1.4441x; 1.4441x over previous
#include <cuda_runtime.h>
#include <cstdint>

#define BATCH 16
#define NANCH 25200
#define NCLS  80
#define TOPK  2048
#define CAND  4096
#define NBIN  16384
#define KBASE 0x3E800000u
#define FULLM 0xFFFFFFFFu

// ---------------- scratch (no allocations allowed) ----------------
__device__ float              g_scores[BATCH * NANCH];
__device__ int                g_labels[BATCH * NANCH];
__device__ unsigned           g_hist[BATCH * NBIN];              // 1MB score histogram
__device__ float              g_top_scores[BATCH * TOPK];
__device__ float4             g_top_boxes[BATCH * TOPK];
__device__ int                g_top_labels[BATCH * TOPK];
__device__ unsigned long long g_mask[(size_t)BATCH * TOPK * 32]; // successor masks (j>i), 8MB
__device__ unsigned long long g_rownz[BATCH * 32];               // per-row nonzero bitmap

// ---------------- Stage 0: zero histogram (graph-replay safe) ----------------
__global__ __launch_bounds__(1024) void k_zero()
{
    g_hist[blockIdx.x * 1024 + threadIdx.x] = 0u;
}

// ---------------- Stage 1: per-anchor max/argmax + fused score histogram ----------------
__global__ __launch_bounds__(256) void k_scores(const float* __restrict__ obj,
                                                const float* __restrict__ cls)
{
    int gwarp = (blockIdx.x * 256 + threadIdx.x) >> 5;
    int lane  = threadIdx.x & 31;
    if (gwarp >= BATCH * NANCH) return;
    const float* p = cls + (size_t)gwarp * NCLS;

    // probs are non-negative -> float bits are order-preserving as u32
    unsigned b0 = __float_as_uint(p[lane]);
    unsigned b1 = __float_as_uint(p[lane + 32]);
    unsigned b2 = (lane < 16) ? __float_as_uint(p[lane + 64]) : 0u;
    unsigned lm = max(b0, max(b1, b2));
    unsigned m  = __reduce_max_sync(FULLM, lm);

    unsigned idx;
    if (b0 == m)                    idx = (unsigned)lane;
    else if (b1 == m)               idx = (unsigned)(lane + 32);
    else if (lane < 16 && b2 == m)  idx = (unsigned)(lane + 64);
    else                            idx = 0x7FFFFFFFu;
    unsigned mi = __reduce_min_sync(FULLM, idx);

    if (lane == 0) {
        float s = obj[gwarp] * __uint_as_float(m);   // == max(obj*p) bitwise
        float sc = (s > 0.25f) ? s : 0.0f;           // conf filter
        g_scores[gwarp] = sc;
        g_labels[gwarp] = (int)mi;
        if (sc > 0.0f) {
            unsigned key = __float_as_uint(sc);      // key in (KBASE, KBASE+2^24]
            unsigned bin = (key - KBASE) >> 10;
            if (bin > NBIN - 1) bin = NBIN - 1;
            atomicAdd(&g_hist[(gwarp / NANCH) * NBIN + bin], 1u);
        }
    }
}

// ---------------- Stage 2: threshold from histogram + gather + exact top-k sort ----------------
__global__ __launch_bounds__(1024) void k_select(const float4* __restrict__ boxes)
{
    __shared__ unsigned long long s_arr[CAND];  // 32KB
    __shared__ int                s_wsum[32];
    __shared__ int                s_L;
    __shared__ int                s_cnt;

    const int b    = blockIdx.x;
    const int tid  = threadIdx.x;
    const int warp = tid >> 5;
    const int lane = tid & 31;
    const unsigned* hist = g_hist + b * NBIN;
    const float* sc = g_scores + b * NANCH;

    // chunk t covers bins [NBIN-16(t+1), NBIN-16t) -- ascending t == descending score
    int hi = NBIN - 16 * tid;
    int sum = 0;
    #pragma unroll
    for (int k = 1; k <= 16; ++k) sum += (int)hist[hi - k];

    // block inclusive scan over t (warp shfl scan + warp-total scan)
    int v = sum;
    #pragma unroll
    for (int off = 1; off < 32; off <<= 1) {
        int n = __shfl_up_sync(FULLM, v, off);
        if (lane >= off) v += n;
    }
    if (lane == 31) s_wsum[warp] = v;
    if (tid == 0) s_L = 0;
    __syncthreads();
    if (warp == 0) {
        int w = s_wsum[lane];
        #pragma unroll
        for (int off = 1; off < 32; off <<= 1) {
            int n = __shfl_up_sync(FULLM, w, off);
            if (lane >= off) w += n;
        }
        s_wsum[lane] = w;
    }
    __syncthreads();
    int cum = v + ((warp > 0) ? s_wsum[warp - 1] : 0);   // inclusive prefix
    int total = s_wsum[31];

    if (total >= TOPK) {
        int prev = cum - sum;                            // exclusive prefix
        if (cum >= TOPK && prev < TOPK) {                // exactly one thread
            int acc = prev, L = 0;
            for (int k = 1; k <= 16; ++k) {
                int bidx = hi - k;
                acc += (int)hist[bidx];
                if (acc >= TOPK) { L = bidx; break; }
            }
            s_L = L;
        }
    }
    if (tid == 0) s_cnt = 0;
    if (tid < 32) g_rownz[b * 32 + tid] = 0ull;          // zero nz bitmap for stage 3
    __syncthreads();
    const int L = s_L;

    // ballot-aggregated gather of all candidates with bin >= L (superset of exact top-K)
    const int iters = (NANCH + 1023) / 1024;             // uniform trip count
    for (int it = 0; it < iters; ++it) {
        int i = tid + it * 1024;
        bool take = false; unsigned k = 0;
        if (i < NANCH) {
            float s = sc[i];
            if (s > 0.0f) {
                k = __float_as_uint(s);
                unsigned bin = (k - KBASE) >> 10;
                if (bin > NBIN - 1) bin = NBIN - 1;
                take = ((int)bin >= L);
            }
        }
        unsigned bal = __ballot_sync(FULLM, take);
        if (bal) {
            int leader = __ffs(bal) - 1;
            int pos = 0;
            if (lane == leader) pos = atomicAdd(&s_cnt, __popc(bal));
            pos = __shfl_sync(FULLM, pos, leader);
            if (take) {
                int my = pos + __popc(bal & ((1u << lane) - 1u));
                if (my < CAND)
                    s_arr[my] = ((unsigned long long)k << 32) | (unsigned)(0xFFFFFFFFu - (unsigned)i);
            }
        }
    }
    __syncthreads();
    int cnt = s_cnt; if (cnt > CAND) cnt = CAND;
    for (int p = cnt + tid; p < CAND; p += 1024) s_arr[p] = 0ull;
    __syncthreads();

    // bitonic sort descending on (score desc, idx asc) -- matches lax.top_k exactly
    for (int kk = 2; kk <= CAND; kk <<= 1) {
        for (int j = kk >> 1; j > 0; j >>= 1) {
            for (int p = tid; p < CAND / 2; p += 1024) {
                int i = ((p & ~(j - 1)) << 1) | (p & (j - 1));
                int l = i | j;
                unsigned long long a = s_arr[i], c = s_arr[l];
                bool desc = ((i & kk) == 0);
                if (desc ? (a < c) : (a > c)) { s_arr[i] = c; s_arr[l] = a; }
            }
            __syncthreads();
        }
    }

    for (int j = tid; j < TOPK; j += 1024) {
        unsigned long long c = s_arr[j];
        unsigned key = (unsigned)(c >> 32);
        int o = b * TOPK + j;
        g_top_scores[o] = __uint_as_float(key);
        if (key) {
            unsigned idx = 0xFFFFFFFFu - (unsigned)(c & 0xFFFFFFFFull);
            g_top_boxes[o]  = boxes[(size_t)b * NANCH + idx];
            g_top_labels[o] = g_labels[b * NANCH + idx];
        } else {
            g_top_boxes[o]  = make_float4(0.f, 0.f, 0.f, 0.f);
            g_top_labels[o] = 0;
        }
    }
}

// ---------------- Stage 3a: successor IoU bitmask -- conflict-free transposed loop ----------------
// Step t: lane l tests j = t*32 + l (consecutive float4 LDS, no bank conflicts).
// Ballot assembles 32 j-bits; lane t>>1 owns them at half-word (t&1)*32.
__global__ __launch_bounds__(1024) void k_mask()
{
    __shared__ float4 sbox[TOPK];   // 32KB
    __shared__ float  sarea[TOPK];  // 8KB
    const int b   = blockIdx.y;
    const int tid = threadIdx.x;
    for (int j = tid; j < TOPK; j += 1024) {
        float4 v = g_top_boxes[b * TOPK + j];
        sbox[j]  = v;
        sarea[j] = (v.z - v.x) * (v.w - v.y);   // same op order as reference
    }
    __syncthreads();

    const int warp = tid >> 5, lane = tid & 31;
    const int i = blockIdx.x * 32 + warp;
    const float4 bi = sbox[i];
    const float  ai = sarea[i];

    unsigned long long word = 0ull;             // lane w owns word w (j in [64w, 64w+64))
    const int t0 = i >> 5;                      // first step whose j-range intersects j > i
    for (int t = t0; t < 64; ++t) {
        int j = t * 32 + lane;
        bool hit = false;
        if (j > i) {
            float4 bj = sbox[j];
            float ltx = fmaxf(bi.x, bj.x), lty = fmaxf(bi.y, bj.y);
            float rbx = fminf(bi.z, bj.z), rby = fminf(bi.w, bj.w);
            float w = rbx - ltx, h = rby - lty;
            if (w > 0.0f && h > 0.0f) {
                float inter = w * h;
                float iou = __fdiv_rn(inter, (ai + sarea[j]) - inter); // IEEE div
                hit = (iou > 0.45f);
            }
        }
        unsigned bal = __ballot_sync(FULLM, hit);
        if (lane == (t >> 1))
            word |= (unsigned long long)bal << ((t & 1) * 32);
    }
    g_mask[((size_t)(b * TOPK + i)) * 32 + lane] = word;
    unsigned nzb = __ballot_sync(FULLM, word != 0ull);
    if (lane == 0 && nzb)
        atomicOr(&g_rownz[b * 32 + (i >> 6)], 1ull << (i & 63));
}

// ---------------- Stage 3b: double-buffered shared-memory greedy resolve (128 thr) ----------------
__global__ __launch_bounds__(128) void k_resolve(float* __restrict__ out_boxes,
                                                 float* __restrict__ out_scores,
                                                 float* __restrict__ out_labels)
{
    __shared__ unsigned long long s_buf[2][64 * 32];   // 2 x 16KB double buffer
    __shared__ unsigned long long s_alive[32], s_keep[32];
    const int b = blockIdx.x, tid = threadIdx.x, warp = tid >> 5, lane = tid & 31;

    // alive bits: each of 4 warps covers 8 chunks of 64 rows
    #pragma unroll
    for (int k = 0; k < 8; ++k) {
        int chunk = warp * 8 + k;
        bool a0 = g_top_scores[b * TOPK + chunk * 64 + lane] > 0.0f;
        bool a1 = g_top_scores[b * TOPK + chunk * 64 + 32 + lane] > 0.0f;
        unsigned lo = __ballot_sync(FULLM, a0);
        unsigned hiv = __ballot_sync(FULLM, a1);
        if (lane == 0) s_alive[chunk] = ((unsigned long long)hiv << 32) | (unsigned long long)lo;
    }

    const unsigned long long* mbase = g_mask + (size_t)b * TOPK * 32;

    for (int i = tid; i < 2048; i += 128) s_buf[0][i] = mbase[i];   // prefetch block 0
    __syncthreads();

    unsigned long long rm = 0ull, alv = 0ull, nzw = 0ull;  // warp 0: lane w owns word w
    if (warp == 0) { nzw = g_rownz[b * 32 + lane]; alv = s_alive[lane]; }

    for (int g = 0; g < 32; ++g) {
        if (warp > 0) {
            if (g < 31) {                                   // producer: prefetch block g+1
                const unsigned long long* src = mbase + (size_t)(g + 1) * 2048;
                unsigned long long* dst = s_buf[(g + 1) & 1];
                for (int i = tid - 32; i < 2048; i += 96) dst[i] = src[i];
            }
        } else {
            const unsigned long long* buf = s_buf[g & 1];   // consumer: resolve block g
            unsigned long long rmB = __shfl_sync(FULLM, rm,  g);
            unsigned long long alB = __shfl_sync(FULLM, alv, g);
            unsigned long long nzB = __shfl_sync(FULLM, nzw, g);
            unsigned long long cand = alB & ~rmB & nzB;     // only rows that can suppress
            unsigned long long rem = 0ull, kept = 0ull;

            while (cand) {                                  // uniform across the warp
                int r = __ffsll((long long)cand) - 1;
                cand &= cand - 1ull;
                kept |= 1ull << r;
                rem  |= buf[r * 32 + g];                    // broadcast LDS (diagonal word)
                cand &= ~rem;
            }
            if (lane == g) rm |= rem;

            unsigned long long a0 = 0, a1 = 0, a2 = 0, a3 = 0;  // rotate 4 accumulators
            unsigned long long kz = kept;
            while (kz) {
                int r0 = __ffsll((long long)kz) - 1; kz &= kz - 1ull;
                a0 |= buf[r0 * 32 + lane];
                if (kz) { int r1 = __ffsll((long long)kz) - 1; kz &= kz - 1ull; a1 |= buf[r1 * 32 + lane]; }
                if (kz) { int r2 = __ffsll((long long)kz) - 1; kz &= kz - 1ull; a2 |= buf[r2 * 32 + lane]; }
                if (kz) { int r3 = __ffsll((long long)kz) - 1; kz &= kz - 1ull; a3 |= buf[r3 * 32 + lane]; }
            }
            rm |= (a0 | a1) | (a2 | a3);
        }
        __syncthreads();
    }

    if (warp == 0) s_keep[lane] = alv & ~rm;
    __syncthreads();

    float4* ob = (float4*)out_boxes;
    for (int j = tid; j < TOPK; j += 128) {
        int o = b * TOPK + j;
        bool kp = ((s_keep[j >> 6] >> (j & 63)) & 1ull) != 0ull;
        float f = kp ? 1.0f : 0.0f;
        float4 bx = g_top_boxes[o];
        ob[o] = make_float4(bx.x * f, bx.y * f, bx.z * f, bx.w * f);
        out_scores[o] = kp ? g_top_scores[o] : 0.0f;
        out_labels[o] = kp ? (float)g_top_labels[o] : 0.0f;
    }
}

// ---------------- launch ----------------
extern "C" void kernel_launch(void* const* d_in, const int* in_sizes, int n_in,
                              void* d_out, int out_size)
{
    const float* boxes = (const float*)d_in[0];   // [16,25200,4]
    const float* obj   = (const float*)d_in[1];   // [16,25200]
    const float* cls   = (const float*)d_in[2];   // [16,25200,80]
    float* out = (float*)d_out;

    (void)in_sizes; (void)n_in; (void)out_size;

    k_zero<<<BATCH * NBIN / 1024, 1024>>>();

    int rows = BATCH * NANCH;
    int blocks1 = (rows * 32 + 255) / 256;         // warp per row
    k_scores<<<blocks1, 256>>>(obj, cls);

    k_select<<<BATCH, 1024>>>((const float4*)boxes);

    dim3 gm(TOPK / 32, BATCH);
    k_mask<<<gm, 1024>>>();

    float* out_boxes  = out;
    float* out_scores = out + (size_t)BATCH * TOPK * 4;
    float* out_labels = out + (size_t)BATCH * TOPK * 5;
    k_resolve<<<BATCH, 128>>>(out_boxes, out_scores, out_labels);
}